// round 9
// baseline (speedup 1.0000x reference)
#include <cuda_runtime.h>
#include <math.h>

#define NN    50000
#define NFEAT 256
#define NHID  128
#define NA    32
#define NP    4

// ---------------- scratch (device globals; no allocation allowed) ----------------
__device__ float g_tmp[NN*NHID];
__device__ float g_h[NN*NHID];
__device__ float g_hx[NN*NP*NHID];      // [n][p*128+j]
__device__ float g_haB[NP*NA*NHID];     // swizzled, see hab_kernel
__device__ float g_attn[NN*NA];
__device__ float g_rowsum[NN];
__device__ float g_colsum[NA];
__device__ float g_support[NN*NHID];
__device__ float g_U[NA*NHID];
__device__ float g_xcA[NN*NHID];
__device__ float g_xcB[NN*NHID];
__device__ float g_t1[NN*NHID];

// ---------------- packed fp32x2 helpers (Blackwell f32x2 pipe) --------------------
__device__ __forceinline__ void fadd2(float& d0, float& d1,
                                      float a0, float a1, float b0, float b1)
{
    asm("{.reg .b64 ra,rb,rd;\n\t"
        "mov.b64 ra,{%2,%3}; mov.b64 rb,{%4,%5};\n\t"
        "add.rn.f32x2 rd,ra,rb;\n\t"
        "mov.b64 {%0,%1},rd;}"
        : "=f"(d0), "=f"(d1) : "f"(a0), "f"(a1), "f"(b0), "f"(b1));
}
__device__ __forceinline__ void ffma2(float& d0, float& d1,
                                      float a0, float a1, float b0, float b1)
{
    asm("{.reg .b64 ra,rb,rc,rd;\n\t"
        "mov.b64 ra,{%2,%3}; mov.b64 rb,{%4,%5}; mov.b64 rc,{%0,%1};\n\t"
        "fma.rn.f32x2 rd,ra,rb,rc;\n\t"
        "mov.b64 {%0,%1},rd;}"
        : "+f"(d0), "+f"(d1) : "f"(a0), "f"(a1), "f"(b0), "f"(b1));
}

// ================= TF32 tensor-core GEMM with fp32-split accuracy ================
// C[M, gridDim.x*128] = act(A[M,K] @ B[K,128](per-x-block) + bias)
// Block 128x128, BK=16, 512 thr, 16 warps (4m x 4n), warp tile 32x32.
// hi/lo split PRECOMPUTED at smem-store time; inner loop = LDS + HMMA only.
//   hi = a & 0xFFFFE000 (exact tf32), lo = a - hi
//   d += ahi*bhi + alo*bhi + ahi*blo   (error ~2^-20)

__device__ __forceinline__ void mma_tf32(float* d, const unsigned* a, const unsigned* b)
{
    asm volatile(
        "mma.sync.aligned.m16n8k8.row.col.f32.tf32.tf32.f32 "
        "{%0,%1,%2,%3}, {%4,%5,%6,%7}, {%8,%9}, {%0,%1,%2,%3};\n"
        : "+f"(d[0]), "+f"(d[1]), "+f"(d[2]), "+f"(d[3])
        : "r"(a[0]), "r"(a[1]), "r"(a[2]), "r"(a[3]),
          "r"(b[0]), "r"(b[1]));
}

__device__ __forceinline__ float f_hi_f(float v) {
    return __uint_as_float(__float_as_uint(v) & 0xffffe000u);
}

// smem: 4 arrays [2 stages][16 k][128 mn] floats
#define TG_IDX(st,k,x) (((st) * 16 + (k)) * 128 + (x))

template<int ACT>
__global__ __launch_bounds__(512, 1) void tgemm_kernel(
    const float* __restrict__ A, const float* __restrict__ B,
    const float* __restrict__ bias, const float* __restrict__ alpha,
    float* __restrict__ C, int M, int K, int lda, long bstride, int ldc)
{
    extern __shared__ float smdyn[];
    float* AsH = smdyn;            // 4096 floats
    float* AsL = smdyn + 4096;
    float* BsH = smdyn + 8192;
    float* BsL = smdyn + 12288;

    const int tid  = threadIdx.x;
    const int lane = tid & 31;
    const int warp = tid >> 5;
    const int wm = warp & 3;          // m offset wm*32
    const int wn = warp >> 2;         // n offset wn*32
    const int g = lane >> 2, t = lane & 3;
    const int by = blockIdx.y * 128;
    const float* Bp = B + (long)blockIdx.x * bstride;
    const int colbase = blockIdx.x * 128;

    // A load: one float4/thread: arow = tid>>2 (0..127), akq = (tid&3)*4
    const int arow = tid >> 2;
    const int akq  = (tid & 3) * 4;
    const bool arow_ok = (by + arow) < M;
    const float* aptr = A + (size_t)(by + arow) * lda + akq;
    // B load: one float4/thread: br = tid>>5 (0..15), bc = (tid&31)*4
    const int br = tid >> 5, bc = (tid & 31) * 4;
    const int bsw = bc ^ (8 * (br & 3));

    const int KT = K / 16;
    float acc[2][4][4];
    #pragma unroll
    for (int mt = 0; mt < 2; mt++)
        #pragma unroll
        for (int nt = 0; nt < 4; nt++)
            #pragma unroll
            for (int j = 0; j < 4; j++) acc[mt][nt][j] = 0.f;

    // ---- load + split tile 0 ----
    {
        float4 a0 = make_float4(0,0,0,0);
        if (arow_ok) a0 = *(const float4*)(aptr);
        #pragma unroll
        for (int i = 0; i < 4; i++) {
            float v = (&a0.x)[i];
            float h = f_hi_f(v);
            AsH[TG_IDX(0, akq + i, arow ^ (8 * i))] = h;
            AsL[TG_IDX(0, akq + i, arow ^ (8 * i))] = v - h;
        }
        float4 b0 = *(const float4*)(Bp + (size_t)br * 128 + bc);
        float4 h0, l0;
        #pragma unroll
        for (int i = 0; i < 4; i++) {
            (&h0.x)[i] = f_hi_f((&b0.x)[i]); (&l0.x)[i] = (&b0.x)[i] - (&h0.x)[i];
        }
        *(float4*)&BsH[TG_IDX(0, br, bsw)] = h0;
        *(float4*)&BsL[TG_IDX(0, br, bsw)] = l0;
    }
    __syncthreads();

    const int swz = 8 * t;

    for (int kt = 0; kt < KT; kt++) {
        const int cur = kt & 1, nxt = cur ^ 1;
        float4 pa0, pb0;
        const bool have_next = (kt + 1) < KT;
        if (have_next) {
            pa0 = make_float4(0,0,0,0);
            if (arow_ok) pa0 = *(const float4*)(aptr + (kt + 1) * 16);
            pb0 = *(const float4*)(Bp + (size_t)(kt + 1) * 16 * 128 + (size_t)br * 128 + bc);
        }

        #pragma unroll
        for (int kc = 0; kc < 16; kc += 8) {
            unsigned ahi[2][4], alo[2][4];
            #pragma unroll
            for (int mt = 0; mt < 2; mt++) {
                const int mb = wm * 32 + mt * 16;
                #pragma unroll
                for (int j = 0; j < 4; j++) {
                    const int k = kc + t + (j >> 1) * 4;
                    const int m = (mb + g + (j & 1) * 8) ^ swz;
                    ahi[mt][j] = __float_as_uint(AsH[TG_IDX(cur, k, m)]);
                    alo[mt][j] = __float_as_uint(AsL[TG_IDX(cur, k, m)]);
                }
            }
            unsigned bhi[4][2], blo[4][2];
            #pragma unroll
            for (int nt = 0; nt < 4; nt++) {
                const int nb = wn * 32 + nt * 8 + g;
                #pragma unroll
                for (int j = 0; j < 2; j++) {
                    const int k = kc + t + j * 4;
                    bhi[nt][j] = __float_as_uint(BsH[TG_IDX(cur, k, nb ^ swz)]);
                    blo[nt][j] = __float_as_uint(BsL[TG_IDX(cur, k, nb ^ swz)]);
                }
            }
            #pragma unroll
            for (int mt = 0; mt < 2; mt++)
                #pragma unroll
                for (int nt = 0; nt < 4; nt++) {
                    mma_tf32(acc[mt][nt], ahi[mt], bhi[nt]);
                    mma_tf32(acc[mt][nt], alo[mt], bhi[nt]);
                    mma_tf32(acc[mt][nt], ahi[mt], blo[nt]);
                }
        }

        if (have_next) {
            #pragma unroll
            for (int i = 0; i < 4; i++) {
                float v = (&pa0.x)[i];
                float h = f_hi_f(v);
                AsH[TG_IDX(nxt, akq + i, arow ^ (8 * i))] = h;
                AsL[TG_IDX(nxt, akq + i, arow ^ (8 * i))] = v - h;
            }
            float4 h0, l0;
            #pragma unroll
            for (int i = 0; i < 4; i++) {
                (&h0.x)[i] = f_hi_f((&pb0.x)[i]); (&l0.x)[i] = (&pb0.x)[i] - (&h0.x)[i];
            }
            *(float4*)&BsH[TG_IDX(nxt, br, bsw)] = h0;
            *(float4*)&BsL[TG_IDX(nxt, br, bsw)] = l0;
        }
        __syncthreads();
    }

    // ---- epilogue ----
    #pragma unroll
    for (int mt = 0; mt < 2; mt++) {
        const int row0 = by + wm * 32 + mt * 16 + g;
        #pragma unroll
        for (int nt = 0; nt < 4; nt++) {
            const int cl = wn * 32 + nt * 8 + 2 * t;
            float b0 = 0.f, b1 = 0.f;
            if (bias) { b0 = bias[cl]; b1 = bias[cl + 1]; }
            float v0 = acc[mt][nt][0] + b0;
            float v1 = acc[mt][nt][1] + b1;
            float v2 = acc[mt][nt][2] + b0;
            float v3 = acc[mt][nt][3] + b1;
            if (ACT == 1) {
                v0 = fmaxf(v0, 0.f); v1 = fmaxf(v1, 0.f);
                v2 = fmaxf(v2, 0.f); v3 = fmaxf(v3, 0.f);
            }
            if (ACT == 2) {
                float a0 = alpha[cl], a1 = alpha[cl + 1];
                v0 = v0 > 0.f ? v0 : a0 * v0;
                v1 = v1 > 0.f ? v1 : a1 * v1;
                v2 = v2 > 0.f ? v2 : a0 * v2;
                v3 = v3 > 0.f ? v3 : a1 * v3;
            }
            if (row0 < M)
                *(float2*)(C + (size_t)row0 * ldc + colbase + cl) = make_float2(v0, v1);
            if (row0 + 8 < M)
                *(float2*)(C + (size_t)(row0 + 8) * ldc + colbase + cl) = make_float2(v2, v3);
        }
    }
}

// ---------------- haB[p][a][j] = (anchors @ Wa[p])[a][j] + ml_b1[p][j], swizzled --
__global__ void hab_kernel(const float* __restrict__ anchors,
                           const float* __restrict__ ml_w1,
                           const float* __restrict__ ml_b1,
                           float* __restrict__ haB)
{
    int a = blockIdx.x, p = blockIdx.y, j = threadIdx.x;
    __shared__ float anc[NHID];
    anc[j] = anchors[a * NHID + j];
    __syncthreads();
    const float* Wa = ml_w1 + ((size_t)p * 2 * NHID + NHID) * NHID;
    float acc = ml_b1[p * NHID + j];
    for (int k = 0; k < NHID; k++)
        acc = fmaf(anc[k], Wa[(size_t)k * NHID + j], acc);
    int slot = ((j >> 2) ^ a) & 31;
    haB[((p * NA + a) * 32 + slot) * 4 + (j & 3)] = acc;
}

// ---------------- fused attention with packed f32x2 inner loop -------------------
__global__ __launch_bounds__(256) void attn_kernel(
    const float* __restrict__ hx, const float* __restrict__ haB,
    const float* __restrict__ ml_w2, const float* __restrict__ ml_b2,
    float* __restrict__ attn, float* __restrict__ rowsum, float* __restrict__ colsum)
{
    extern __shared__ float sm[];
    float* hxs  = sm;              // 8192 floats
    float* haBs = sm + 8192;       // 16384 floats
    float* w2s  = sm + 24576;      // 512 floats
    float* sAtt = sm + 25088;      // 512 floats

    const int tid = threadIdx.x;
    const int a = tid & 31, p = (tid >> 5) & 3, r = tid >> 7;
    const int node0 = blockIdx.x * 16;

    const float4* hxg = (const float4*)(hx + (size_t)node0 * NP * NHID);
    float4* hxsv = (float4*)hxs;
    for (int i = tid; i < 2048; i += 256) hxsv[i] = hxg[i];
    const float4* hbg = (const float4*)haB;
    float4* hbv = (float4*)haBs;
    for (int i = tid; i < 4096; i += 256) hbv[i] = hbg[i];
    for (int i = tid; i < 512; i += 256) w2s[i] = ml_w2[i];
    for (int i = tid; i < 512; i += 256) sAtt[i] = 0.f;
    __syncthreads();

    const float4* hxv = (const float4*)hxs;
    const float4* hav = (const float4*)haBs;
    const float4* w2v = (const float4*)w2s;
    const int n0 = r * 8;
    const float4* myhx = hxv + n0 * 128 + p * 32;
    const float4* myha = hav + (p * 32 + a) * 32;
    const float4* myw  = w2v + p * 32;

    float acc0[8], acc1[8], acc2[8], acc3[8];
    #pragma unroll
    for (int n = 0; n < 8; n++) { acc0[n]=0.f; acc1[n]=0.f; acc2[n]=0.f; acc3[n]=0.f; }

    #pragma unroll 2
    for (int j4 = 0; j4 < 32; j4++) {
        float4 ha = myha[(j4 ^ a) & 31];
        float4 w  = myw[j4];
        #pragma unroll
        for (int n = 0; n < 8; n++) {
            float4 hh = myhx[n * 128 + j4];
            float t0, t1, t2, t3;
            fadd2(t0, t1, hh.x, hh.y, ha.x, ha.y);
            fadd2(t2, t3, hh.z, hh.w, ha.z, ha.w);
            t0 = fmaxf(t0, 0.f); t1 = fmaxf(t1, 0.f);
            t2 = fmaxf(t2, 0.f); t3 = fmaxf(t3, 0.f);
            ffma2(acc0[n], acc1[n], t0, t1, w.x, w.y);
            ffma2(acc2[n], acc3[n], t2, t3, w.z, w.w);
        }
    }
    const float b2p = ml_b2[p];
    #pragma unroll
    for (int n = 0; n < 8; n++) {
        float av = (acc0[n] + acc1[n]) + (acc2[n] + acc3[n]);
        float s = 1.f / (1.f + __expf(-(av + b2p)));
        atomicAdd(&sAtt[(n0 + n) * NA + a], s);
    }
    __syncthreads();

    for (int i = tid; i < 512; i += 256) attn[(size_t)node0 * NA + i] = sAtt[i];
    if (tid < 16) {
        float s = 0.f;
        #pragma unroll
        for (int aa = 0; aa < NA; aa++) s += sAtt[tid * NA + aa];
        rowsum[node0 + tid] = s;
    }
    if (tid < NA) {
        float s = 0.f;
        #pragma unroll
        for (int n = 0; n < 16; n++) s += sAtt[n * NA + tid];
        atomicAdd(&colsum[tid], s);
    }
}

// ---------------- U[a][j] += sum_n attn[n][a] * support[n][j] (split-K + atomics) -
__global__ __launch_bounds__(256) void agg_kernel(
    const float* __restrict__ attn, const float* __restrict__ support,
    float* __restrict__ U, int N)
{
    __shared__ float sA[32][32];
    const int tid = threadIdx.x;
    const int j = tid & 127, half = tid >> 7;
    const int node0 = blockIdx.x * 256;
    float acc[16];
    #pragma unroll
    for (int i = 0; i < 16; i++) acc[i] = 0.f;

    for (int base = 0; base < 256; base += 32) {
        __syncthreads();
        for (int idx = tid; idx < 1024; idx += 256) {
            int nn = idx >> 5, aa = idx & 31;
            int n = node0 + base + nn;
            sA[nn][aa] = (n < N) ? attn[(size_t)n * NA + aa] : 0.f;
        }
        __syncthreads();
        for (int nn = 0; nn < 32; nn++) {
            int n = node0 + base + nn;
            float s = (n < N) ? support[(size_t)n * NHID + j] : 0.f;
            #pragma unroll
            for (int i = 0; i < 16; i++)
                acc[i] = fmaf(s, sA[nn][half * 16 + i], acc[i]);
        }
    }
    #pragma unroll
    for (int i = 0; i < 16; i++)
        atomicAdd(&U[(half * 16 + i) * NHID + j], acc[i]);
}

// ---------------- xc[n][j] = relu( invr * sum_a attn[n][a]*(U[a][j]/colsum[a]) + b[j] )
__global__ __launch_bounds__(128) void xc_kernel(
    const float* __restrict__ attn, const float* __restrict__ rowsum,
    const float* __restrict__ colsum, const float* __restrict__ U,
    const float* __restrict__ bias, float* __restrict__ xc, int N)
{
    __shared__ float Us[NA * NHID];
    __shared__ float incs[NA];
    __shared__ float wa[4][NA];
    const int tid = threadIdx.x;
    if (tid < NA) incs[tid] = 1.f / fmaxf(colsum[tid], 1e-12f);
    __syncthreads();
    for (int idx = tid; idx < NA * NHID; idx += 128)
        Us[idx] = U[idx] * incs[idx >> 7];
    const float bj = bias[tid];
    const int node0 = blockIdx.x * 32;
    for (int nb = 0; nb < 32; nb += 4) {
        __syncthreads();
        if (tid < 128) {
            int nn = tid >> 5, aa = tid & 31;
            int node = node0 + nb + nn;
            wa[nn][aa] = (node < N) ? attn[(size_t)node * NA + aa] : 0.f;
        }
        __syncthreads();
        #pragma unroll
        for (int nn = 0; nn < 4; nn++) {
            int node = node0 + nb + nn;
            if (node >= N) break;
            float invr = 1.f / fmaxf(rowsum[node], 1e-12f);
            float acc = 0.f;
            #pragma unroll
            for (int a = 0; a < NA; a++)
                acc = fmaf(wa[nn][a], Us[a * NHID + tid], acc);
            xc[(size_t)node * NHID + tid] = fmaxf(acc * invr + bj, 0.f);
        }
    }
}

// ---------------- z = LN(xc + h) * g + b ; warp per node --------------------------
__global__ __launch_bounds__(256) void ln_kernel(
    const float* __restrict__ xc, const float* __restrict__ h,
    const float* __restrict__ g, const float* __restrict__ b,
    float* __restrict__ zout, int N)
{
    const int warp = threadIdx.x >> 5, lane = threadIdx.x & 31;
    const int node = blockIdx.x * 8 + warp;
    if (node >= N) return;
    const float4* xv = (const float4*)(xc + (size_t)node * NHID);
    const float4* hv = (const float4*)(h + (size_t)node * NHID);
    float4 xa = xv[lane], hb = hv[lane];
    float4 z = make_float4(xa.x + hb.x, xa.y + hb.y, xa.z + hb.z, xa.w + hb.w);
    float s1 = z.x + z.y + z.z + z.w;
    float s2 = z.x * z.x + z.y * z.y + z.z * z.z + z.w * z.w;
    #pragma unroll
    for (int o = 16; o > 0; o >>= 1) {
        s1 += __shfl_xor_sync(0xffffffffu, s1, o);
        s2 += __shfl_xor_sync(0xffffffffu, s2, o);
    }
    const float mu = s1 * (1.f / 128.f);
    const float var = s2 * (1.f / 128.f) - mu * mu;
    const float rs = rsqrtf(var + 1e-5f);
    float4 g4 = ((const float4*)g)[lane];
    float4 b4 = ((const float4*)b)[lane];
    float4 o4;
    o4.x = (z.x - mu) * rs * g4.x + b4.x;
    o4.y = (z.y - mu) * rs * g4.y + b4.y;
    o4.z = (z.z - mu) * rs * g4.z + b4.z;
    o4.w = (z.w - mu) * rs * g4.w + b4.w;
    ((float4*)(zout + (size_t)node * NHID))[lane] = o4;
}

// ---------------- pred[n][0..1] = t1[n] @ cls_w2 + cls_b2 ; warp per node ---------
__global__ __launch_bounds__(256) void pred_kernel(
    const float* __restrict__ t1, const float* __restrict__ cls_w2,
    const float* __restrict__ cls_b2, float* __restrict__ pred, int N)
{
    const int warp = threadIdx.x >> 5, lane = threadIdx.x & 31;
    const int node = blockIdx.x * 8 + warp;
    if (node >= N) return;
    float4 t = ((const float4*)(t1 + (size_t)node * NHID))[lane];
    const float4* wv = (const float4*)cls_w2;
    float4 wA = wv[lane * 2], wB = wv[lane * 2 + 1];
    float a0 = t.x * wA.x + t.y * wA.z + t.z * wB.x + t.w * wB.z;
    float a1 = t.x * wA.y + t.y * wA.w + t.z * wB.y + t.w * wB.w;
    #pragma unroll
    for (int o = 16; o > 0; o >>= 1) {
        a0 += __shfl_xor_sync(0xffffffffu, a0, o);
        a1 += __shfl_xor_sync(0xffffffffu, a1, o);
    }
    if (lane == 0) {
        pred[(size_t)node * 2 + 0] = a0 + cls_b2[0];
        pred[(size_t)node * 2 + 1] = a1 + cls_b2[1];
    }
}

// ---------------- anchors: copy anchor_vec + anchor classifier --------------------
__global__ __launch_bounds__(128) void anchor_kernel(
    const float* __restrict__ anchors, const float* __restrict__ cls_w1,
    const float* __restrict__ cls_b1, const float* __restrict__ prelu,
    const float* __restrict__ cls_w2, const float* __restrict__ cls_b2,
    float* __restrict__ avec, float* __restrict__ alog)
{
    __shared__ float t1s[NA * NHID];
    const int j = threadIdx.x;
    for (int idx = j; idx < NA * NHID; idx += 128) avec[idx] = anchors[idx];
    for (int aa = 0; aa < NA; aa++) {
        float acc = cls_b1[j];
        for (int k = 0; k < NHID; k++)
            acc = fmaf(anchors[aa * NHID + k], cls_w1[k * NHID + j], acc);
        t1s[aa * NHID + j] = acc > 0.f ? acc : prelu[j] * acc;
    }
    __syncthreads();
    if (j < 64) {
        int a = j >> 1, c = j & 1;
        float acc = cls_b2[c];
        for (int k = 0; k < NHID; k++)
            acc = fmaf(t1s[a * NHID + k], cls_w2[k * 2 + c], acc);
        alog[j] = acc;
    }
}

// =================================================================================
extern "C" void kernel_launch(void* const* d_in, const int* in_sizes, int n_in,
                              void* d_out, int out_size)
{
    const float* x       = (const float*)d_in[0];
    const float* im_w1   = (const float*)d_in[1];
    const float* im_b1   = (const float*)d_in[2];
    const float* im_w2   = (const float*)d_in[3];
    const float* im_b2   = (const float*)d_in[4];
    const float* anchors = (const float*)d_in[5];
    const float* ml_w1   = (const float*)d_in[6];
    const float* ml_b1   = (const float*)d_in[7];
    const float* ml_w2   = (const float*)d_in[8];
    const float* ml_b2   = (const float*)d_in[9];
    const float* enc_w   = (const float*)d_in[10];
    const float* enc_b   = (const float*)d_in[11];
    const float* ln_g    = (const float*)d_in[12];
    const float* ln_b    = (const float*)d_in[13];
    const float* cls_w1  = (const float*)d_in[14];
    const float* cls_b1  = (const float*)d_in[15];
    const float* prelu_a = (const float*)d_in[16];
    const float* cls_w2  = (const float*)d_in[17];
    const float* cls_b2  = (const float*)d_in[18];

    float* out = (float*)d_out;
    float* out_pred = out;                       // [50000, 2]
    float* out_z    = out + 100000;              // [50000, 128]
    float* out_avec = out + 100000 + NN * NHID;  // [1, 32, 128]
    float* out_alog = out_avec + NA * NHID;      // [32, 2]

    float *p_tmp, *p_h, *p_hx, *p_haB, *p_attn, *p_rowsum, *p_colsum;
    float *p_support, *p_U, *p_xcA, *p_xcB, *p_t1;
    cudaGetSymbolAddress((void**)&p_tmp,     g_tmp);
    cudaGetSymbolAddress((void**)&p_h,       g_h);
    cudaGetSymbolAddress((void**)&p_hx,      g_hx);
    cudaGetSymbolAddress((void**)&p_haB,     g_haB);
    cudaGetSymbolAddress((void**)&p_attn,    g_attn);
    cudaGetSymbolAddress((void**)&p_rowsum,  g_rowsum);
    cudaGetSymbolAddress((void**)&p_colsum,  g_colsum);
    cudaGetSymbolAddress((void**)&p_support, g_support);
    cudaGetSymbolAddress((void**)&p_U,       g_U);
    cudaGetSymbolAddress((void**)&p_xcA,     g_xcA);
    cudaGetSymbolAddress((void**)&p_xcB,     g_xcB);
    cudaGetSymbolAddress((void**)&p_t1,      g_t1);

    const int MB = (NN + 127) / 128;             // 391
    const dim3 g1(1, MB);
    const int TG_SMEM = 65536;

    cudaFuncSetAttribute(tgemm_kernel<0>, cudaFuncAttributeMaxDynamicSharedMemorySize, TG_SMEM);
    cudaFuncSetAttribute(tgemm_kernel<1>, cudaFuncAttributeMaxDynamicSharedMemorySize, TG_SMEM);
    cudaFuncSetAttribute(tgemm_kernel<2>, cudaFuncAttributeMaxDynamicSharedMemorySize, TG_SMEM);
    cudaFuncSetAttribute(attn_kernel, cudaFuncAttributeMaxDynamicSharedMemorySize, 102400);

    // anchor-side precomputes (independent)
    hab_kernel<<<dim3(NA, NP), NHID>>>(anchors, ml_w1, ml_b1, p_haB);
    anchor_kernel<<<1, 128>>>(anchors, cls_w1, cls_b1, prelu_a, cls_w2, cls_b2,
                              out_avec, out_alog);

    // input MLP: h = relu(x@W1+b1)@W2+b2
    tgemm_kernel<1><<<g1, 512, TG_SMEM>>>(x, im_w1, im_b1, nullptr, p_tmp,
                                          NN, NFEAT, NFEAT, 0, NHID);
    tgemm_kernel<0><<<g1, 512, TG_SMEM>>>(p_tmp, im_w2, im_b2, nullptr, p_h,
                                          NN, NHID, NHID, 0, NHID);

    // hx[p] = h @ Wx[p] -> interleaved [n][p*128+j], fused: grid.x = p
    tgemm_kernel<0><<<dim3(NP, MB), 512, TG_SMEM>>>(p_h, ml_w1, nullptr, nullptr,
                                                    p_hx, NN, NHID, NHID,
                                                    (long)2 * NHID * NHID, NP * NHID);

    cudaMemsetAsync(p_colsum, 0, NA * sizeof(float));
    attn_kernel<<<NN / 16, 256, 102400>>>(p_hx, p_haB, ml_w2, ml_b2,
                                          p_attn, p_rowsum, p_colsum);

    // 2-hop encoder
    const float* xc_in = p_h;
    float* xcs[2] = { p_xcA, p_xcB };
    for (int hop = 0; hop < 2; hop++) {
        tgemm_kernel<0><<<g1, 512, TG_SMEM>>>(xc_in, enc_w + (size_t)hop * NHID * NHID,
                                              nullptr, nullptr, p_support,
                                              NN, NHID, NHID, 0, NHID);
        cudaMemsetAsync(p_U, 0, NA * NHID * sizeof(float));
        agg_kernel<<<(NN + 255) / 256, 256>>>(p_attn, p_support, p_U, NN);
        xc_kernel<<<(NN + 31) / 32, 128>>>(p_attn, p_rowsum, p_colsum, p_U,
                                           enc_b + hop * NHID, xcs[hop], NN);
        xc_in = xcs[hop];
    }

    // z = LN(xc + h) -> out_z ; classifier
    ln_kernel<<<NN / 8, 256>>>(xc_in, p_h, ln_g, ln_b, out_z, NN);
    tgemm_kernel<2><<<g1, 512, TG_SMEM>>>(out_z, cls_w1, cls_b1, prelu_a, p_t1,
                                          NN, NHID, NHID, 0, NHID);
    pred_kernel<<<NN / 8, 256>>>(p_t1, cls_w2, cls_b2, out_pred, NN);
}

// round 11
// speedup vs baseline: 1.0639x; 1.0639x over previous
#include <cuda_runtime.h>
#include <math.h>

#define NN    50000
#define NFEAT 256
#define NHID  128
#define NA    32
#define NP    4

// ---------------- scratch (device globals; no allocation allowed) ----------------
__device__ float g_tmp[NN*NHID];
__device__ float g_h[NN*NHID];
__device__ float g_hx[NN*NP*NHID];      // [n][p*128+j]
__device__ float g_haB[NP*NA*NHID];     // swizzled, see hab_kernel
__device__ float g_attn[NN*NA];
__device__ float g_rowsum[NN];
__device__ float g_colsum[NA];
__device__ float g_support[NN*NHID];
__device__ float g_U[NA*NHID];
__device__ float g_xcA[NN*NHID];
__device__ float g_xcB[NN*NHID];
__device__ float g_t1[NN*NHID];

// ---------------- packed fp32x2 helpers (Blackwell f32x2 pipe) --------------------
__device__ __forceinline__ void fadd2(float& d0, float& d1,
                                      float a0, float a1, float b0, float b1)
{
    asm("{.reg .b64 ra,rb,rd;\n\t"
        "mov.b64 ra,{%2,%3}; mov.b64 rb,{%4,%5};\n\t"
        "add.rn.f32x2 rd,ra,rb;\n\t"
        "mov.b64 {%0,%1},rd;}"
        : "=f"(d0), "=f"(d1) : "f"(a0), "f"(a1), "f"(b0), "f"(b1));
}
__device__ __forceinline__ void ffma2(float& d0, float& d1,
                                      float a0, float a1, float b0, float b1)
{
    asm("{.reg .b64 ra,rb,rc,rd;\n\t"
        "mov.b64 ra,{%2,%3}; mov.b64 rb,{%4,%5}; mov.b64 rc,{%0,%1};\n\t"
        "fma.rn.f32x2 rd,ra,rb,rc;\n\t"
        "mov.b64 {%0,%1},rd;}"
        : "+f"(d0), "+f"(d1) : "f"(a0), "f"(a1), "f"(b0), "f"(b1));
}

// ================= TF32 tensor-core GEMM, split-2 (tf32x2-rna) ===================
// C[M, gridDim.x*128] = act(A[M,K] @ B[K,128](per-x-block) + bias)
// Block 128x128, BK=16, 512 thr, 16 warps (4m x 4n), warp tile 32x32.
//   ahi = rna_tf32(a), alo = a - ahi, bh = rna_tf32(b)
//   d += ahi*bh + alo*bh      (dropped term a*(b-bh): |rel| <= 2^-14)
// hi/lo/bh all PRECOMPUTED at smem-store time; inner loop = LDS + HMMA only.

__device__ __forceinline__ void mma_tf32(float* d, const unsigned* a, const unsigned* b)
{
    asm volatile(
        "mma.sync.aligned.m16n8k8.row.col.f32.tf32.tf32.f32 "
        "{%0,%1,%2,%3}, {%4,%5,%6,%7}, {%8,%9}, {%0,%1,%2,%3};\n"
        : "+f"(d[0]), "+f"(d[1]), "+f"(d[2]), "+f"(d[3])
        : "r"(a[0]), "r"(a[1]), "r"(a[2]), "r"(a[3]),
          "r"(b[0]), "r"(b[1]));
}

__device__ __forceinline__ float f_rna(float v) {
    unsigned r;
    asm("cvt.rna.tf32.f32 %0, %1;" : "=r"(r) : "f"(v));
    return __uint_as_float(r);
}

// smem: 3 arrays [2 stages][16 k][128 mn] floats
#define TG_IDX(st,k,x) (((st) * 16 + (k)) * 128 + (x))

template<int ACT>
__global__ __launch_bounds__(512, 1) void tgemm_kernel(
    const float* __restrict__ A, const float* __restrict__ B,
    const float* __restrict__ bias, const float* __restrict__ alpha,
    float* __restrict__ C, int M, int K, int lda, long bstride, int ldc)
{
    extern __shared__ float smdyn[];
    float* AsH = smdyn;            // 4096 floats
    float* AsL = smdyn + 4096;
    float* BsH = smdyn + 8192;

    const int tid  = threadIdx.x;
    const int lane = tid & 31;
    const int warp = tid >> 5;
    const int wm = warp & 3;          // m offset wm*32
    const int wn = warp >> 2;         // n offset wn*32
    const int g = lane >> 2, t = lane & 3;
    const int by = blockIdx.y * 128;
    const float* Bp = B + (long)blockIdx.x * bstride;
    const int colbase = blockIdx.x * 128;

    // A load: one float4/thread: arow = tid>>2 (0..127), akq = (tid&3)*4
    const int arow = tid >> 2;
    const int akq  = (tid & 3) * 4;
    const bool arow_ok = (by + arow) < M;
    const float* aptr = A + (size_t)(by + arow) * lda + akq;
    // B load: one float4/thread: br = tid>>5 (0..15), bc = (tid&31)*4
    const int br = tid >> 5, bc = (tid & 31) * 4;
    const int bsw = bc ^ (8 * (br & 3));

    const int KT = K / 16;
    float acc[2][4][4];
    #pragma unroll
    for (int mt = 0; mt < 2; mt++)
        #pragma unroll
        for (int nt = 0; nt < 4; nt++)
            #pragma unroll
            for (int j = 0; j < 4; j++) acc[mt][nt][j] = 0.f;

    // ---- load + split tile 0 ----
    {
        float4 a0 = make_float4(0,0,0,0);
        if (arow_ok) a0 = *(const float4*)(aptr);
        #pragma unroll
        for (int i = 0; i < 4; i++) {
            float v = (&a0.x)[i];
            float h = f_rna(v);
            AsH[TG_IDX(0, akq + i, arow ^ (8 * i))] = h;
            AsL[TG_IDX(0, akq + i, arow ^ (8 * i))] = v - h;
        }
        float4 b0 = *(const float4*)(Bp + (size_t)br * 128 + bc);
        float4 h0;
        #pragma unroll
        for (int i = 0; i < 4; i++) (&h0.x)[i] = f_rna((&b0.x)[i]);
        *(float4*)&BsH[TG_IDX(0, br, bsw)] = h0;
    }
    __syncthreads();

    const int swz = 8 * t;

    for (int kt = 0; kt < KT; kt++) {
        const int cur = kt & 1, nxt = cur ^ 1;
        float4 pa0, pb0;
        const bool have_next = (kt + 1) < KT;
        if (have_next) {
            pa0 = make_float4(0,0,0,0);
            if (arow_ok) pa0 = *(const float4*)(aptr + (kt + 1) * 16);
            pb0 = *(const float4*)(Bp + (size_t)(kt + 1) * 16 * 128 + (size_t)br * 128 + bc);
        }

        #pragma unroll
        for (int kc = 0; kc < 16; kc += 8) {
            unsigned ahi[2][4], alo[2][4];
            #pragma unroll
            for (int mt = 0; mt < 2; mt++) {
                const int mb = wm * 32 + mt * 16;
                #pragma unroll
                for (int j = 0; j < 4; j++) {
                    const int k = kc + t + (j >> 1) * 4;
                    const int m = (mb + g + (j & 1) * 8) ^ swz;
                    ahi[mt][j] = __float_as_uint(AsH[TG_IDX(cur, k, m)]);
                    alo[mt][j] = __float_as_uint(AsL[TG_IDX(cur, k, m)]);
                }
            }
            unsigned bhi[4][2];
            #pragma unroll
            for (int nt = 0; nt < 4; nt++) {
                const int nb = wn * 32 + nt * 8 + g;
                #pragma unroll
                for (int j = 0; j < 2; j++) {
                    const int k = kc + t + j * 4;
                    bhi[nt][j] = __float_as_uint(BsH[TG_IDX(cur, k, nb ^ swz)]);
                }
            }
            #pragma unroll
            for (int mt = 0; mt < 2; mt++)
                #pragma unroll
                for (int nt = 0; nt < 4; nt++) {
                    mma_tf32(acc[mt][nt], ahi[mt], bhi[nt]);
                    mma_tf32(acc[mt][nt], alo[mt], bhi[nt]);
                }
        }

        if (have_next) {
            #pragma unroll
            for (int i = 0; i < 4; i++) {
                float v = (&pa0.x)[i];
                float h = f_rna(v);
                AsH[TG_IDX(nxt, akq + i, arow ^ (8 * i))] = h;
                AsL[TG_IDX(nxt, akq + i, arow ^ (8 * i))] = v - h;
            }
            float4 h0;
            #pragma unroll
            for (int i = 0; i < 4; i++) (&h0.x)[i] = f_rna((&pb0.x)[i]);
            *(float4*)&BsH[TG_IDX(nxt, br, bsw)] = h0;
        }
        __syncthreads();
    }

    // ---- epilogue ----
    #pragma unroll
    for (int mt = 0; mt < 2; mt++) {
        const int row0 = by + wm * 32 + mt * 16 + g;
        #pragma unroll
        for (int nt = 0; nt < 4; nt++) {
            const int cl = wn * 32 + nt * 8 + 2 * t;
            float b0 = 0.f, b1 = 0.f;
            if (bias) { b0 = bias[cl]; b1 = bias[cl + 1]; }
            float v0 = acc[mt][nt][0] + b0;
            float v1 = acc[mt][nt][1] + b1;
            float v2 = acc[mt][nt][2] + b0;
            float v3 = acc[mt][nt][3] + b1;
            if (ACT == 1) {
                v0 = fmaxf(v0, 0.f); v1 = fmaxf(v1, 0.f);
                v2 = fmaxf(v2, 0.f); v3 = fmaxf(v3, 0.f);
            }
            if (ACT == 2) {
                float a0 = alpha[cl], a1 = alpha[cl + 1];
                v0 = v0 > 0.f ? v0 : a0 * v0;
                v1 = v1 > 0.f ? v1 : a1 * v1;
                v2 = v2 > 0.f ? v2 : a0 * v2;
                v3 = v3 > 0.f ? v3 : a1 * v3;
            }
            if (row0 < M)
                *(float2*)(C + (size_t)row0 * ldc + colbase + cl) = make_float2(v0, v1);
            if (row0 + 8 < M)
                *(float2*)(C + (size_t)(row0 + 8) * ldc + colbase + cl) = make_float2(v2, v3);
        }
    }
}

// ---------------- haB[p][a][j] = (anchors @ Wa[p])[a][j] + ml_b1[p][j], swizzled --
__global__ void hab_kernel(const float* __restrict__ anchors,
                           const float* __restrict__ ml_w1,
                           const float* __restrict__ ml_b1,
                           float* __restrict__ haB)
{
    int a = blockIdx.x, p = blockIdx.y, j = threadIdx.x;
    __shared__ float anc[NHID];
    anc[j] = anchors[a * NHID + j];
    __syncthreads();
    const float* Wa = ml_w1 + ((size_t)p * 2 * NHID + NHID) * NHID;
    float acc = ml_b1[p * NHID + j];
    for (int k = 0; k < NHID; k++)
        acc = fmaf(anc[k], Wa[(size_t)k * NHID + j], acc);
    int slot = ((j >> 2) ^ a) & 31;
    haB[((p * NA + a) * 32 + slot) * 4 + (j & 3)] = acc;
}

// ---------------- fused attention with packed f32x2 inner loop -------------------
__global__ __launch_bounds__(256) void attn_kernel(
    const float* __restrict__ hx, const float* __restrict__ haB,
    const float* __restrict__ ml_w2, const float* __restrict__ ml_b2,
    float* __restrict__ attn, float* __restrict__ rowsum, float* __restrict__ colsum)
{
    extern __shared__ float sm[];
    float* hxs  = sm;              // 8192 floats
    float* haBs = sm + 8192;       // 16384 floats
    float* w2s  = sm + 24576;      // 512 floats
    float* sAtt = sm + 25088;      // 512 floats

    const int tid = threadIdx.x;
    const int a = tid & 31, p = (tid >> 5) & 3, r = tid >> 7;
    const int node0 = blockIdx.x * 16;

    const float4* hxg = (const float4*)(hx + (size_t)node0 * NP * NHID);
    float4* hxsv = (float4*)hxs;
    for (int i = tid; i < 2048; i += 256) hxsv[i] = hxg[i];
    const float4* hbg = (const float4*)haB;
    float4* hbv = (float4*)haBs;
    for (int i = tid; i < 4096; i += 256) hbv[i] = hbg[i];
    for (int i = tid; i < 512; i += 256) w2s[i] = ml_w2[i];
    for (int i = tid; i < 512; i += 256) sAtt[i] = 0.f;
    __syncthreads();

    const float4* hxv = (const float4*)hxs;
    const float4* hav = (const float4*)haBs;
    const float4* w2v = (const float4*)w2s;
    const int n0 = r * 8;
    const float4* myhx = hxv + n0 * 128 + p * 32;
    const float4* myha = hav + (p * 32 + a) * 32;
    const float4* myw  = w2v + p * 32;

    float acc0[8], acc1[8], acc2[8], acc3[8];
    #pragma unroll
    for (int n = 0; n < 8; n++) { acc0[n]=0.f; acc1[n]=0.f; acc2[n]=0.f; acc3[n]=0.f; }

    #pragma unroll 2
    for (int j4 = 0; j4 < 32; j4++) {
        float4 ha = myha[(j4 ^ a) & 31];
        float4 w  = myw[j4];
        #pragma unroll
        for (int n = 0; n < 8; n++) {
            float4 hh = myhx[n * 128 + j4];
            float t0, t1, t2, t3;
            fadd2(t0, t1, hh.x, hh.y, ha.x, ha.y);
            fadd2(t2, t3, hh.z, hh.w, ha.z, ha.w);
            t0 = fmaxf(t0, 0.f); t1 = fmaxf(t1, 0.f);
            t2 = fmaxf(t2, 0.f); t3 = fmaxf(t3, 0.f);
            ffma2(acc0[n], acc1[n], t0, t1, w.x, w.y);
            ffma2(acc2[n], acc3[n], t2, t3, w.z, w.w);
        }
    }
    const float b2p = ml_b2[p];
    #pragma unroll
    for (int n = 0; n < 8; n++) {
        float av = (acc0[n] + acc1[n]) + (acc2[n] + acc3[n]);
        float s = 1.f / (1.f + __expf(-(av + b2p)));
        atomicAdd(&sAtt[(n0 + n) * NA + a], s);
    }
    __syncthreads();

    for (int i = tid; i < 512; i += 256) attn[(size_t)node0 * NA + i] = sAtt[i];
    if (tid < 16) {
        float s = 0.f;
        #pragma unroll
        for (int aa = 0; aa < NA; aa++) s += sAtt[tid * NA + aa];
        rowsum[node0 + tid] = s;
    }
    if (tid < NA) {
        float s = 0.f;
        #pragma unroll
        for (int n = 0; n < 16; n++) s += sAtt[n * NA + tid];
        atomicAdd(&colsum[tid], s);
    }
}

// ---------------- U[a][j] += sum_n attn[n][a] * support[n][j] (split-K + atomics) -
__global__ __launch_bounds__(256) void agg_kernel(
    const float* __restrict__ attn, const float* __restrict__ support,
    float* __restrict__ U, int N)
{
    __shared__ float sA[32][32];
    const int tid = threadIdx.x;
    const int j = tid & 127, half = tid >> 7;
    const int node0 = blockIdx.x * 256;
    float acc[16];
    #pragma unroll
    for (int i = 0; i < 16; i++) acc[i] = 0.f;

    for (int base = 0; base < 256; base += 32) {
        __syncthreads();
        for (int idx = tid; idx < 1024; idx += 256) {
            int nn = idx >> 5, aa = idx & 31;
            int n = node0 + base + nn;
            sA[nn][aa] = (n < N) ? attn[(size_t)n * NA + aa] : 0.f;
        }
        __syncthreads();
        for (int nn = 0; nn < 32; nn++) {
            int n = node0 + base + nn;
            float s = (n < N) ? support[(size_t)n * NHID + j] : 0.f;
            #pragma unroll
            for (int i = 0; i < 16; i++)
                acc[i] = fmaf(s, sA[nn][half * 16 + i], acc[i]);
        }
    }
    #pragma unroll
    for (int i = 0; i < 16; i++)
        atomicAdd(&U[(half * 16 + i) * NHID + j], acc[i]);
}

// ---------------- xc[n][j] = relu( invr * sum_a attn[n][a]*(U[a][j]/colsum[a]) + b[j] )
__global__ __launch_bounds__(128) void xc_kernel(
    const float* __restrict__ attn, const float* __restrict__ rowsum,
    const float* __restrict__ colsum, const float* __restrict__ U,
    const float* __restrict__ bias, float* __restrict__ xc, int N)
{
    __shared__ float Us[NA * NHID];
    __shared__ float incs[NA];
    __shared__ float wa[4][NA];
    const int tid = threadIdx.x;
    if (tid < NA) incs[tid] = 1.f / fmaxf(colsum[tid], 1e-12f);
    __syncthreads();
    for (int idx = tid; idx < NA * NHID; idx += 128)
        Us[idx] = U[idx] * incs[idx >> 7];
    const float bj = bias[tid];
    const int node0 = blockIdx.x * 32;
    for (int nb = 0; nb < 32; nb += 4) {
        __syncthreads();
        if (tid < 128) {
            int nn = tid >> 5, aa = tid & 31;
            int node = node0 + nb + nn;
            wa[nn][aa] = (node < N) ? attn[(size_t)node * NA + aa] : 0.f;
        }
        __syncthreads();
        #pragma unroll
        for (int nn = 0; nn < 4; nn++) {
            int node = node0 + nb + nn;
            if (node >= N) break;
            float invr = 1.f / fmaxf(rowsum[node], 1e-12f);
            float acc = 0.f;
            #pragma unroll
            for (int a = 0; a < NA; a++)
                acc = fmaf(wa[nn][a], Us[a * NHID + tid], acc);
            xc[(size_t)node * NHID + tid] = fmaxf(acc * invr + bj, 0.f);
        }
    }
}

// ---------------- z = LN(xc + h) * g + b ; warp per node --------------------------
__global__ __launch_bounds__(256) void ln_kernel(
    const float* __restrict__ xc, const float* __restrict__ h,
    const float* __restrict__ g, const float* __restrict__ b,
    float* __restrict__ zout, int N)
{
    const int warp = threadIdx.x >> 5, lane = threadIdx.x & 31;
    const int node = blockIdx.x * 8 + warp;
    if (node >= N) return;
    const float4* xv = (const float4*)(xc + (size_t)node * NHID);
    const float4* hv = (const float4*)(h + (size_t)node * NHID);
    float4 xa = xv[lane], hb = hv[lane];
    float4 z = make_float4(xa.x + hb.x, xa.y + hb.y, xa.z + hb.z, xa.w + hb.w);
    float s1 = z.x + z.y + z.z + z.w;
    float s2 = z.x * z.x + z.y * z.y + z.z * z.z + z.w * z.w;
    #pragma unroll
    for (int o = 16; o > 0; o >>= 1) {
        s1 += __shfl_xor_sync(0xffffffffu, s1, o);
        s2 += __shfl_xor_sync(0xffffffffu, s2, o);
    }
    const float mu = s1 * (1.f / 128.f);
    const float var = s2 * (1.f / 128.f) - mu * mu;
    const float rs = rsqrtf(var + 1e-5f);
    float4 g4 = ((const float4*)g)[lane];
    float4 b4 = ((const float4*)b)[lane];
    float4 o4;
    o4.x = (z.x - mu) * rs * g4.x + b4.x;
    o4.y = (z.y - mu) * rs * g4.y + b4.y;
    o4.z = (z.z - mu) * rs * g4.z + b4.z;
    o4.w = (z.w - mu) * rs * g4.w + b4.w;
    ((float4*)(zout + (size_t)node * NHID))[lane] = o4;
}

// ---------------- pred[n][0..1] = t1[n] @ cls_w2 + cls_b2 ; warp per node ---------
__global__ __launch_bounds__(256) void pred_kernel(
    const float* __restrict__ t1, const float* __restrict__ cls_w2,
    const float* __restrict__ cls_b2, float* __restrict__ pred, int N)
{
    const int warp = threadIdx.x >> 5, lane = threadIdx.x & 31;
    const int node = blockIdx.x * 8 + warp;
    if (node >= N) return;
    float4 t = ((const float4*)(t1 + (size_t)node * NHID))[lane];
    const float4* wv = (const float4*)cls_w2;
    float4 wA = wv[lane * 2], wB = wv[lane * 2 + 1];
    float a0 = t.x * wA.x + t.y * wA.z + t.z * wB.x + t.w * wB.z;
    float a1 = t.x * wA.y + t.y * wA.w + t.z * wB.y + t.w * wB.w;
    #pragma unroll
    for (int o = 16; o > 0; o >>= 1) {
        a0 += __shfl_xor_sync(0xffffffffu, a0, o);
        a1 += __shfl_xor_sync(0xffffffffu, a1, o);
    }
    if (lane == 0) {
        pred[(size_t)node * 2 + 0] = a0 + cls_b2[0];
        pred[(size_t)node * 2 + 1] = a1 + cls_b2[1];
    }
}

// ---------------- anchors: copy anchor_vec + anchor classifier --------------------
__global__ __launch_bounds__(128) void anchor_kernel(
    const float* __restrict__ anchors, const float* __restrict__ cls_w1,
    const float* __restrict__ cls_b1, const float* __restrict__ prelu,
    const float* __restrict__ cls_w2, const float* __restrict__ cls_b2,
    float* __restrict__ avec, float* __restrict__ alog)
{
    __shared__ float t1s[NA * NHID];
    const int j = threadIdx.x;
    for (int idx = j; idx < NA * NHID; idx += 128) avec[idx] = anchors[idx];
    for (int aa = 0; aa < NA; aa++) {
        float acc = cls_b1[j];
        for (int k = 0; k < NHID; k++)
            acc = fmaf(anchors[aa * NHID + k], cls_w1[k * NHID + j], acc);
        t1s[aa * NHID + j] = acc > 0.f ? acc : prelu[j] * acc;
    }
    __syncthreads();
    if (j < 64) {
        int a = j >> 1, c = j & 1;
        float acc = cls_b2[c];
        for (int k = 0; k < NHID; k++)
            acc = fmaf(t1s[a * NHID + k], cls_w2[k * 2 + c], acc);
        alog[j] = acc;
    }
}

// =================================================================================
extern "C" void kernel_launch(void* const* d_in, const int* in_sizes, int n_in,
                              void* d_out, int out_size)
{
    const float* x       = (const float*)d_in[0];
    const float* im_w1   = (const float*)d_in[1];
    const float* im_b1   = (const float*)d_in[2];
    const float* im_w2   = (const float*)d_in[3];
    const float* im_b2   = (const float*)d_in[4];
    const float* anchors = (const float*)d_in[5];
    const float* ml_w1   = (const float*)d_in[6];
    const float* ml_b1   = (const float*)d_in[7];
    const float* ml_w2   = (const float*)d_in[8];
    const float* ml_b2   = (const float*)d_in[9];
    const float* enc_w   = (const float*)d_in[10];
    const float* enc_b   = (const float*)d_in[11];
    const float* ln_g    = (const float*)d_in[12];
    const float* ln_b    = (const float*)d_in[13];
    const float* cls_w1  = (const float*)d_in[14];
    const float* cls_b1  = (const float*)d_in[15];
    const float* prelu_a = (const float*)d_in[16];
    const float* cls_w2  = (const float*)d_in[17];
    const float* cls_b2  = (const float*)d_in[18];

    float* out = (float*)d_out;
    float* out_pred = out;                       // [50000, 2]
    float* out_z    = out + 100000;              // [50000, 128]
    float* out_avec = out + 100000 + NN * NHID;  // [1, 32, 128]
    float* out_alog = out_avec + NA * NHID;      // [32, 2]

    float *p_tmp, *p_h, *p_hx, *p_haB, *p_attn, *p_rowsum, *p_colsum;
    float *p_support, *p_U, *p_xcA, *p_xcB, *p_t1;
    cudaGetSymbolAddress((void**)&p_tmp,     g_tmp);
    cudaGetSymbolAddress((void**)&p_h,       g_h);
    cudaGetSymbolAddress((void**)&p_hx,      g_hx);
    cudaGetSymbolAddress((void**)&p_haB,     g_haB);
    cudaGetSymbolAddress((void**)&p_attn,    g_attn);
    cudaGetSymbolAddress((void**)&p_rowsum,  g_rowsum);
    cudaGetSymbolAddress((void**)&p_colsum,  g_colsum);
    cudaGetSymbolAddress((void**)&p_support, g_support);
    cudaGetSymbolAddress((void**)&p_U,       g_U);
    cudaGetSymbolAddress((void**)&p_xcA,     g_xcA);
    cudaGetSymbolAddress((void**)&p_xcB,     g_xcB);
    cudaGetSymbolAddress((void**)&p_t1,      g_t1);

    const int MB = (NN + 127) / 128;             // 391
    const dim3 g1(1, MB);
    const int TG_SMEM = 49152;                   // 3 arrays * 2 stages * 2048 floats

    cudaFuncSetAttribute(tgemm_kernel<0>, cudaFuncAttributeMaxDynamicSharedMemorySize, TG_SMEM);
    cudaFuncSetAttribute(tgemm_kernel<1>, cudaFuncAttributeMaxDynamicSharedMemorySize, TG_SMEM);
    cudaFuncSetAttribute(tgemm_kernel<2>, cudaFuncAttributeMaxDynamicSharedMemorySize, TG_SMEM);
    cudaFuncSetAttribute(attn_kernel, cudaFuncAttributeMaxDynamicSharedMemorySize, 102400);

    // anchor-side precomputes (independent)
    hab_kernel<<<dim3(NA, NP), NHID>>>(anchors, ml_w1, ml_b1, p_haB);
    anchor_kernel<<<1, 128>>>(anchors, cls_w1, cls_b1, prelu_a, cls_w2, cls_b2,
                              out_avec, out_alog);

    // input MLP: h = relu(x@W1+b1)@W2+b2
    tgemm_kernel<1><<<g1, 512, TG_SMEM>>>(x, im_w1, im_b1, nullptr, p_tmp,
                                          NN, NFEAT, NFEAT, 0, NHID);
    tgemm_kernel<0><<<g1, 512, TG_SMEM>>>(p_tmp, im_w2, im_b2, nullptr, p_h,
                                          NN, NHID, NHID, 0, NHID);

    // hx[p] = h @ Wx[p] -> interleaved [n][p*128+j], fused: grid.x = p
    tgemm_kernel<0><<<dim3(NP, MB), 512, TG_SMEM>>>(p_h, ml_w1, nullptr, nullptr,
                                                    p_hx, NN, NHID, NHID,
                                                    (long)2 * NHID * NHID, NP * NHID);

    cudaMemsetAsync(p_colsum, 0, NA * sizeof(float));
    attn_kernel<<<NN / 16, 256, 102400>>>(p_hx, p_haB, ml_w2, ml_b2,
                                          p_attn, p_rowsum, p_colsum);

    // 2-hop encoder
    const float* xc_in = p_h;
    float* xcs[2] = { p_xcA, p_xcB };
    for (int hop = 0; hop < 2; hop++) {
        tgemm_kernel<0><<<g1, 512, TG_SMEM>>>(xc_in, enc_w + (size_t)hop * NHID * NHID,
                                              nullptr, nullptr, p_support,
                                              NN, NHID, NHID, 0, NHID);
        cudaMemsetAsync(p_U, 0, NA * NHID * sizeof(float));
        agg_kernel<<<(NN + 255) / 256, 256>>>(p_attn, p_support, p_U, NN);
        xc_kernel<<<(NN + 31) / 32, 128>>>(p_attn, p_rowsum, p_colsum, p_U,
                                           enc_b + hop * NHID, xcs[hop], NN);
        xc_in = xcs[hop];
    }

    // z = LN(xc + h) -> out_z ; classifier
    ln_kernel<<<NN / 8, 256>>>(xc_in, p_h, ln_g, ln_b, out_z, NN);
    tgemm_kernel<2><<<g1, 512, TG_SMEM>>>(out_z, cls_w1, cls_b1, prelu_a, p_t1,
                                          NN, NHID, NHID, 0, NHID);
    pred_kernel<<<NN / 8, 256>>>(p_t1, cls_w2, cls_b2, out_pred, NN);
}

// round 12
// speedup vs baseline: 1.1137x; 1.0469x over previous
#include <cuda_runtime.h>
#include <cuda_bf16.h>
#include <math.h>

#define NN    50000
#define NFEAT 256
#define NHID  128
#define NA    32
#define NP    4

// ---------------- scratch (device globals; no allocation allowed) ----------------
__device__ float g_tmp[NN*NHID];
__device__ float g_h[NN*NHID];
__device__ float g_hx[NN*NP*NHID];      // [n][p*128+j]
__device__ float g_haB[NP*NA*NHID];     // swizzled, see hab_kernel
__device__ float g_attn[NN*NA];
__device__ float g_rowsum[NN];
__device__ float g_colsum[NA];
__device__ float g_support[NN*NHID];
__device__ float g_U[NA*NHID];
__device__ float g_xcA[NN*NHID];
__device__ float g_xcB[NN*NHID];
__device__ float g_t1[NN*NHID];

// ---------------- packed fp32x2 helpers (Blackwell f32x2 pipe) --------------------
__device__ __forceinline__ void fadd2(float& d0, float& d1,
                                      float a0, float a1, float b0, float b1)
{
    asm("{.reg .b64 ra,rb,rd;\n\t"
        "mov.b64 ra,{%2,%3}; mov.b64 rb,{%4,%5};\n\t"
        "add.rn.f32x2 rd,ra,rb;\n\t"
        "mov.b64 {%0,%1},rd;}"
        : "=f"(d0), "=f"(d1) : "f"(a0), "f"(a1), "f"(b0), "f"(b1));
}
__device__ __forceinline__ void ffma2(float& d0, float& d1,
                                      float a0, float a1, float b0, float b1)
{
    asm("{.reg .b64 ra,rb,rc,rd;\n\t"
        "mov.b64 ra,{%2,%3}; mov.b64 rb,{%4,%5}; mov.b64 rc,{%0,%1};\n\t"
        "fma.rn.f32x2 rd,ra,rb,rc;\n\t"
        "mov.b64 {%0,%1},rd;}"
        : "+f"(d0), "+f"(d1) : "f"(a0), "f"(a1), "f"(b0), "f"(b1));
}

// ================= BF16 tensor-core GEMM, split-3 (bf16x2 accuracy) ==============
// C[M, gridDim.x*128] = act(A[M,K] @ B[K,128](per-x-block) + bias)
// Block 128x128, BK=16, 512 thr, 16 warps (4m x 4n), warp tile 32x32,
// mma.sync.m16n8k16.bf16 (one slab covers the whole BK=16 per warp tile).
//   ah = bf16(a), al = bf16(a - ah); bh/bl same
//   d += ah*bh + al*bh + ah*bl      (dropped terms ~3*2^-18 per element)
// Split precomputed at smem-store time; smem holds packed bf16x2 (pairs along k):
//   As*[kp][m], Bs*[kp][n], kp = k/2, entry = (elem k=2kp in lo16, k=2kp+1 in hi16)

__device__ __forceinline__ void mma_bf16(float* d, const unsigned* a, const unsigned* b)
{
    asm volatile(
        "mma.sync.aligned.m16n8k16.row.col.f32.bf16.bf16.f32 "
        "{%0,%1,%2,%3}, {%4,%5,%6,%7}, {%8,%9}, {%0,%1,%2,%3};\n"
        : "+f"(d[0]), "+f"(d[1]), "+f"(d[2]), "+f"(d[3])
        : "r"(a[0]), "r"(a[1]), "r"(a[2]), "r"(a[3]),
          "r"(b[0]), "r"(b[1]));
}

// pack two floats to bf16x2: lo_elem -> bits[0:16), hi_elem -> bits[16:32)
__device__ __forceinline__ unsigned bpack(float lo_elem, float hi_elem) {
    unsigned r;
    asm("cvt.rn.bf16x2.f32 %0, %1, %2;" : "=r"(r) : "f"(hi_elem), "f"(lo_elem));
    return r;
}
__device__ __forceinline__ void bsplit(float v, float& hf, float& lf) {
    hf = __bfloat162float(__float2bfloat16(v));
    lf = v - hf;
}

// smem: 4 arrays of unsigned [2 stages][8 kp][128 mn]
#define TG_IDX2(st,kp,x) (((st) * 8 + (kp)) * 128 + (x))

template<int ACT>
__global__ __launch_bounds__(512, 1) void tgemm_kernel(
    const float* __restrict__ A, const float* __restrict__ B,
    const float* __restrict__ bias, const float* __restrict__ alpha,
    float* __restrict__ C, int M, int K, int lda, long bstride, int ldc)
{
    extern __shared__ unsigned smdyn_u[];
    unsigned* AsH = smdyn_u;            // 2048 u32 each
    unsigned* AsL = smdyn_u + 2048;
    unsigned* BsH = smdyn_u + 4096;
    unsigned* BsL = smdyn_u + 6144;

    const int tid  = threadIdx.x;
    const int lane = tid & 31;
    const int warp = tid >> 5;
    const int wm = warp & 3;          // m offset wm*32
    const int wn = warp >> 2;         // n offset wn*32
    const int g = lane >> 2, t = lane & 3;
    const int by = blockIdx.y * 128;
    const float* Bp = B + (long)blockIdx.x * bstride;
    const int colbase = blockIdx.x * 128;

    // A load: one float4/thread: arow = tid>>2 (0..127), k quad = (tid&3)*4
    const int arow = tid >> 2;
    const int akq  = (tid & 3) * 4;
    const int kp0  = (tid & 3) * 2, kp1 = kp0 + 1;
    const int asw0 = arow ^ (8 * (kp0 & 3));
    const int asw1 = arow ^ (8 * (kp1 & 3));
    const bool arow_ok = (by + arow) < M;
    const float* aptr = A + (size_t)(by + arow) * lda + akq;
    // B load: rows pair (2*bkp, 2*bkp+1), cols bn..bn+1 (two float2 loads)
    const int bkp = tid >> 6;          // 0..7
    const int bn  = (tid & 63) * 2;    // 0..126 even
    const int bswz = 8 * (bkp & 3);
    const int bidx = bn ^ bswz;        // even; bn+1 maps to bidx+1

    const int KT = K / 16;
    float acc[2][4][4];
    #pragma unroll
    for (int mt = 0; mt < 2; mt++)
        #pragma unroll
        for (int nt = 0; nt < 4; nt++)
            #pragma unroll
            for (int j = 0; j < 4; j++) acc[mt][nt][j] = 0.f;

    // ---- load + split + pack tile 0 ----
    {
        float4 a0 = make_float4(0,0,0,0);
        if (arow_ok) a0 = *(const float4*)(aptr);
        float h0,h1,h2,h3,l0,l1,l2,l3;
        bsplit(a0.x,h0,l0); bsplit(a0.y,h1,l1); bsplit(a0.z,h2,l2); bsplit(a0.w,h3,l3);
        AsH[TG_IDX2(0, kp0, asw0)] = bpack(h0, h1);
        AsL[TG_IDX2(0, kp0, asw0)] = bpack(l0, l1);
        AsH[TG_IDX2(0, kp1, asw1)] = bpack(h2, h3);
        AsL[TG_IDX2(0, kp1, asw1)] = bpack(l2, l3);

        const float* bp = Bp + (size_t)(2 * bkp) * 128 + bn;
        float2 r0 = *(const float2*)bp;
        float2 r1 = *(const float2*)(bp + 128);
        float h00,l00,h10,l10,h01,l01,h11,l11;
        bsplit(r0.x,h00,l00); bsplit(r1.x,h10,l10);
        bsplit(r0.y,h01,l01); bsplit(r1.y,h11,l11);
        uint2 ph = make_uint2(bpack(h00, h10), bpack(h01, h11));
        uint2 pl = make_uint2(bpack(l00, l10), bpack(l01, l11));
        *(uint2*)&BsH[TG_IDX2(0, bkp, bidx)] = ph;
        *(uint2*)&BsL[TG_IDX2(0, bkp, bidx)] = pl;
    }
    __syncthreads();

    const int swz = 8 * t;

    for (int kt = 0; kt < KT; kt++) {
        const int cur = kt & 1, nxt = cur ^ 1;
        float4 pa0; float2 pr0, pr1;
        const bool have_next = (kt + 1) < KT;
        if (have_next) {
            pa0 = make_float4(0,0,0,0);
            if (arow_ok) pa0 = *(const float4*)(aptr + (kt + 1) * 16);
            const float* bp = Bp + (size_t)((kt + 1) * 16 + 2 * bkp) * 128 + bn;
            pr0 = *(const float2*)bp;
            pr1 = *(const float2*)(bp + 128);
        }

        // ---- one m16n8k16 slab covers BK=16 ----
        unsigned ahi[2][4], alo[2][4];
        #pragma unroll
        for (int mt = 0; mt < 2; mt++) {
            const int mb = wm * 32 + mt * 16;
            #pragma unroll
            for (int j = 0; j < 4; j++) {
                const int kp = t + (j >> 1) * 4;
                const int m = (mb + g + (j & 1) * 8) ^ swz;
                ahi[mt][j] = AsH[TG_IDX2(cur, kp, m)];
                alo[mt][j] = AsL[TG_IDX2(cur, kp, m)];
            }
        }
        unsigned bhi[4][2], blo[4][2];
        #pragma unroll
        for (int nt = 0; nt < 4; nt++) {
            const int nb = (wn * 32 + nt * 8 + g) ^ swz;
            #pragma unroll
            for (int j = 0; j < 2; j++) {
                const int kp = t + j * 4;
                bhi[nt][j] = BsH[TG_IDX2(cur, kp, nb)];
                blo[nt][j] = BsL[TG_IDX2(cur, kp, nb)];
            }
        }
        #pragma unroll
        for (int mt = 0; mt < 2; mt++)
            #pragma unroll
            for (int nt = 0; nt < 4; nt++) {
                mma_bf16(acc[mt][nt], ahi[mt], bhi[nt]);
                mma_bf16(acc[mt][nt], alo[mt], bhi[nt]);
                mma_bf16(acc[mt][nt], ahi[mt], blo[nt]);
            }

        if (have_next) {
            float h0,h1,h2,h3,l0,l1,l2,l3;
            bsplit(pa0.x,h0,l0); bsplit(pa0.y,h1,l1);
            bsplit(pa0.z,h2,l2); bsplit(pa0.w,h3,l3);
            AsH[TG_IDX2(nxt, kp0, asw0)] = bpack(h0, h1);
            AsL[TG_IDX2(nxt, kp0, asw0)] = bpack(l0, l1);
            AsH[TG_IDX2(nxt, kp1, asw1)] = bpack(h2, h3);
            AsL[TG_IDX2(nxt, kp1, asw1)] = bpack(l2, l3);
            float h00,l00,h10,l10,h01,l01,h11,l11;
            bsplit(pr0.x,h00,l00); bsplit(pr1.x,h10,l10);
            bsplit(pr0.y,h01,l01); bsplit(pr1.y,h11,l11);
            uint2 ph = make_uint2(bpack(h00, h10), bpack(h01, h11));
            uint2 pl = make_uint2(bpack(l00, l10), bpack(l01, l11));
            *(uint2*)&BsH[TG_IDX2(nxt, bkp, bidx)] = ph;
            *(uint2*)&BsL[TG_IDX2(nxt, bkp, bidx)] = pl;
        }
        __syncthreads();
    }

    // ---- epilogue ----
    #pragma unroll
    for (int mt = 0; mt < 2; mt++) {
        const int row0 = by + wm * 32 + mt * 16 + g;
        #pragma unroll
        for (int nt = 0; nt < 4; nt++) {
            const int cl = wn * 32 + nt * 8 + 2 * t;
            float b0 = 0.f, b1 = 0.f;
            if (bias) { b0 = bias[cl]; b1 = bias[cl + 1]; }
            float v0 = acc[mt][nt][0] + b0;
            float v1 = acc[mt][nt][1] + b1;
            float v2 = acc[mt][nt][2] + b0;
            float v3 = acc[mt][nt][3] + b1;
            if (ACT == 1) {
                v0 = fmaxf(v0, 0.f); v1 = fmaxf(v1, 0.f);
                v2 = fmaxf(v2, 0.f); v3 = fmaxf(v3, 0.f);
            }
            if (ACT == 2) {
                float a0 = alpha[cl], a1 = alpha[cl + 1];
                v0 = v0 > 0.f ? v0 : a0 * v0;
                v1 = v1 > 0.f ? v1 : a1 * v1;
                v2 = v2 > 0.f ? v2 : a0 * v2;
                v3 = v3 > 0.f ? v3 : a1 * v3;
            }
            if (row0 < M)
                *(float2*)(C + (size_t)row0 * ldc + colbase + cl) = make_float2(v0, v1);
            if (row0 + 8 < M)
                *(float2*)(C + (size_t)(row0 + 8) * ldc + colbase + cl) = make_float2(v2, v3);
        }
    }
}

// ---------------- haB[p][a][j] = (anchors @ Wa[p])[a][j] + ml_b1[p][j], swizzled --
__global__ void hab_kernel(const float* __restrict__ anchors,
                           const float* __restrict__ ml_w1,
                           const float* __restrict__ ml_b1,
                           float* __restrict__ haB)
{
    int a = blockIdx.x, p = blockIdx.y, j = threadIdx.x;
    __shared__ float anc[NHID];
    anc[j] = anchors[a * NHID + j];
    __syncthreads();
    const float* Wa = ml_w1 + ((size_t)p * 2 * NHID + NHID) * NHID;
    float acc = ml_b1[p * NHID + j];
    for (int k = 0; k < NHID; k++)
        acc = fmaf(anc[k], Wa[(size_t)k * NHID + j], acc);
    int slot = ((j >> 2) ^ a) & 31;
    haB[((p * NA + a) * 32 + slot) * 4 + (j & 3)] = acc;
}

// ---------------- fused attention with packed f32x2 inner loop -------------------
__global__ __launch_bounds__(256) void attn_kernel(
    const float* __restrict__ hx, const float* __restrict__ haB,
    const float* __restrict__ ml_w2, const float* __restrict__ ml_b2,
    float* __restrict__ attn, float* __restrict__ rowsum, float* __restrict__ colsum)
{
    extern __shared__ float sm[];
    float* hxs  = sm;              // 8192 floats
    float* haBs = sm + 8192;       // 16384 floats
    float* w2s  = sm + 24576;      // 512 floats
    float* sAtt = sm + 25088;      // 512 floats

    const int tid = threadIdx.x;
    const int a = tid & 31, p = (tid >> 5) & 3, r = tid >> 7;
    const int node0 = blockIdx.x * 16;

    const float4* hxg = (const float4*)(hx + (size_t)node0 * NP * NHID);
    float4* hxsv = (float4*)hxs;
    for (int i = tid; i < 2048; i += 256) hxsv[i] = hxg[i];
    const float4* hbg = (const float4*)haB;
    float4* hbv = (float4*)haBs;
    for (int i = tid; i < 4096; i += 256) hbv[i] = hbg[i];
    for (int i = tid; i < 512; i += 256) w2s[i] = ml_w2[i];
    for (int i = tid; i < 512; i += 256) sAtt[i] = 0.f;
    __syncthreads();

    const float4* hxv = (const float4*)hxs;
    const float4* hav = (const float4*)haBs;
    const float4* w2v = (const float4*)w2s;
    const int n0 = r * 8;
    const float4* myhx = hxv + n0 * 128 + p * 32;
    const float4* myha = hav + (p * 32 + a) * 32;
    const float4* myw  = w2v + p * 32;

    float acc0[8], acc1[8], acc2[8], acc3[8];
    #pragma unroll
    for (int n = 0; n < 8; n++) { acc0[n]=0.f; acc1[n]=0.f; acc2[n]=0.f; acc3[n]=0.f; }

    #pragma unroll 2
    for (int j4 = 0; j4 < 32; j4++) {
        float4 ha = myha[(j4 ^ a) & 31];
        float4 w  = myw[j4];
        #pragma unroll
        for (int n = 0; n < 8; n++) {
            float4 hh = myhx[n * 128 + j4];
            float t0, t1, t2, t3;
            fadd2(t0, t1, hh.x, hh.y, ha.x, ha.y);
            fadd2(t2, t3, hh.z, hh.w, ha.z, ha.w);
            t0 = fmaxf(t0, 0.f); t1 = fmaxf(t1, 0.f);
            t2 = fmaxf(t2, 0.f); t3 = fmaxf(t3, 0.f);
            ffma2(acc0[n], acc1[n], t0, t1, w.x, w.y);
            ffma2(acc2[n], acc3[n], t2, t3, w.z, w.w);
        }
    }
    const float b2p = ml_b2[p];
    #pragma unroll
    for (int n = 0; n < 8; n++) {
        float av = (acc0[n] + acc1[n]) + (acc2[n] + acc3[n]);
        float s = 1.f / (1.f + __expf(-(av + b2p)));
        atomicAdd(&sAtt[(n0 + n) * NA + a], s);
    }
    __syncthreads();

    for (int i = tid; i < 512; i += 256) attn[(size_t)node0 * NA + i] = sAtt[i];
    if (tid < 16) {
        float s = 0.f;
        #pragma unroll
        for (int aa = 0; aa < NA; aa++) s += sAtt[tid * NA + aa];
        rowsum[node0 + tid] = s;
    }
    if (tid < NA) {
        float s = 0.f;
        #pragma unroll
        for (int n = 0; n < 16; n++) s += sAtt[n * NA + tid];
        atomicAdd(&colsum[tid], s);
    }
}

// ---------------- U[a][j] += sum_n attn[n][a] * support[n][j] (split-K + atomics) -
__global__ __launch_bounds__(256) void agg_kernel(
    const float* __restrict__ attn, const float* __restrict__ support,
    float* __restrict__ U, int N)
{
    __shared__ float sA[32][32];
    const int tid = threadIdx.x;
    const int j = tid & 127, half = tid >> 7;
    const int node0 = blockIdx.x * 256;
    float acc[16];
    #pragma unroll
    for (int i = 0; i < 16; i++) acc[i] = 0.f;

    for (int base = 0; base < 256; base += 32) {
        __syncthreads();
        for (int idx = tid; idx < 1024; idx += 256) {
            int nn = idx >> 5, aa = idx & 31;
            int n = node0 + base + nn;
            sA[nn][aa] = (n < N) ? attn[(size_t)n * NA + aa] : 0.f;
        }
        __syncthreads();
        for (int nn = 0; nn < 32; nn++) {
            int n = node0 + base + nn;
            float s = (n < N) ? support[(size_t)n * NHID + j] : 0.f;
            #pragma unroll
            for (int i = 0; i < 16; i++)
                acc[i] = fmaf(s, sA[nn][half * 16 + i], acc[i]);
        }
    }
    #pragma unroll
    for (int i = 0; i < 16; i++)
        atomicAdd(&U[(half * 16 + i) * NHID + j], acc[i]);
}

// ---------------- xc[n][j] = relu( invr * sum_a attn[n][a]*(U[a][j]/colsum[a]) + b[j] )
__global__ __launch_bounds__(128) void xc_kernel(
    const float* __restrict__ attn, const float* __restrict__ rowsum,
    const float* __restrict__ colsum, const float* __restrict__ U,
    const float* __restrict__ bias, float* __restrict__ xc, int N)
{
    __shared__ float Us[NA * NHID];
    __shared__ float incs[NA];
    __shared__ float wa[4][NA];
    const int tid = threadIdx.x;
    if (tid < NA) incs[tid] = 1.f / fmaxf(colsum[tid], 1e-12f);
    __syncthreads();
    for (int idx = tid; idx < NA * NHID; idx += 128)
        Us[idx] = U[idx] * incs[idx >> 7];
    const float bj = bias[tid];
    const int node0 = blockIdx.x * 32;
    for (int nb = 0; nb < 32; nb += 4) {
        __syncthreads();
        if (tid < 128) {
            int nn = tid >> 5, aa = tid & 31;
            int node = node0 + nb + nn;
            wa[nn][aa] = (node < N) ? attn[(size_t)node * NA + aa] : 0.f;
        }
        __syncthreads();
        #pragma unroll
        for (int nn = 0; nn < 4; nn++) {
            int node = node0 + nb + nn;
            if (node >= N) break;
            float invr = 1.f / fmaxf(rowsum[node], 1e-12f);
            float acc = 0.f;
            #pragma unroll
            for (int a = 0; a < NA; a++)
                acc = fmaf(wa[nn][a], Us[a * NHID + tid], acc);
            xc[(size_t)node * NHID + tid] = fmaxf(acc * invr + bj, 0.f);
        }
    }
}

// ---------------- z = LN(xc + h) * g + b ; warp per node --------------------------
__global__ __launch_bounds__(256) void ln_kernel(
    const float* __restrict__ xc, const float* __restrict__ h,
    const float* __restrict__ g, const float* __restrict__ b,
    float* __restrict__ zout, int N)
{
    const int warp = threadIdx.x >> 5, lane = threadIdx.x & 31;
    const int node = blockIdx.x * 8 + warp;
    if (node >= N) return;
    const float4* xv = (const float4*)(xc + (size_t)node * NHID);
    const float4* hv = (const float4*)(h + (size_t)node * NHID);
    float4 xa = xv[lane], hb = hv[lane];
    float4 z = make_float4(xa.x + hb.x, xa.y + hb.y, xa.z + hb.z, xa.w + hb.w);
    float s1 = z.x + z.y + z.z + z.w;
    float s2 = z.x * z.x + z.y * z.y + z.z * z.z + z.w * z.w;
    #pragma unroll
    for (int o = 16; o > 0; o >>= 1) {
        s1 += __shfl_xor_sync(0xffffffffu, s1, o);
        s2 += __shfl_xor_sync(0xffffffffu, s2, o);
    }
    const float mu = s1 * (1.f / 128.f);
    const float var = s2 * (1.f / 128.f) - mu * mu;
    const float rs = rsqrtf(var + 1e-5f);
    float4 g4 = ((const float4*)g)[lane];
    float4 b4 = ((const float4*)b)[lane];
    float4 o4;
    o4.x = (z.x - mu) * rs * g4.x + b4.x;
    o4.y = (z.y - mu) * rs * g4.y + b4.y;
    o4.z = (z.z - mu) * rs * g4.z + b4.z;
    o4.w = (z.w - mu) * rs * g4.w + b4.w;
    ((float4*)(zout + (size_t)node * NHID))[lane] = o4;
}

// ---------------- pred[n][0..1] = t1[n] @ cls_w2 + cls_b2 ; warp per node ---------
__global__ __launch_bounds__(256) void pred_kernel(
    const float* __restrict__ t1, const float* __restrict__ cls_w2,
    const float* __restrict__ cls_b2, float* __restrict__ pred, int N)
{
    const int warp = threadIdx.x >> 5, lane = threadIdx.x & 31;
    const int node = blockIdx.x * 8 + warp;
    if (node >= N) return;
    float4 t = ((const float4*)(t1 + (size_t)node * NHID))[lane];
    const float4* wv = (const float4*)cls_w2;
    float4 wA = wv[lane * 2], wB = wv[lane * 2 + 1];
    float a0 = t.x * wA.x + t.y * wA.z + t.z * wB.x + t.w * wB.z;
    float a1 = t.x * wA.y + t.y * wA.w + t.z * wB.y + t.w * wB.w;
    #pragma unroll
    for (int o = 16; o > 0; o >>= 1) {
        a0 += __shfl_xor_sync(0xffffffffu, a0, o);
        a1 += __shfl_xor_sync(0xffffffffu, a1, o);
    }
    if (lane == 0) {
        pred[(size_t)node * 2 + 0] = a0 + cls_b2[0];
        pred[(size_t)node * 2 + 1] = a1 + cls_b2[1];
    }
}

// ---------------- anchors: copy anchor_vec + anchor classifier --------------------
__global__ __launch_bounds__(128) void anchor_kernel(
    const float* __restrict__ anchors, const float* __restrict__ cls_w1,
    const float* __restrict__ cls_b1, const float* __restrict__ prelu,
    const float* __restrict__ cls_w2, const float* __restrict__ cls_b2,
    float* __restrict__ avec, float* __restrict__ alog)
{
    __shared__ float t1s[NA * NHID];
    const int j = threadIdx.x;
    for (int idx = j; idx < NA * NHID; idx += 128) avec[idx] = anchors[idx];
    for (int aa = 0; aa < NA; aa++) {
        float acc = cls_b1[j];
        for (int k = 0; k < NHID; k++)
            acc = fmaf(anchors[aa * NHID + k], cls_w1[k * NHID + j], acc);
        t1s[aa * NHID + j] = acc > 0.f ? acc : prelu[j] * acc;
    }
    __syncthreads();
    if (j < 64) {
        int a = j >> 1, c = j & 1;
        float acc = cls_b2[c];
        for (int k = 0; k < NHID; k++)
            acc = fmaf(t1s[a * NHID + k], cls_w2[k * 2 + c], acc);
        alog[j] = acc;
    }
}

// =================================================================================
extern "C" void kernel_launch(void* const* d_in, const int* in_sizes, int n_in,
                              void* d_out, int out_size)
{
    const float* x       = (const float*)d_in[0];
    const float* im_w1   = (const float*)d_in[1];
    const float* im_b1   = (const float*)d_in[2];
    const float* im_w2   = (const float*)d_in[3];
    const float* im_b2   = (const float*)d_in[4];
    const float* anchors = (const float*)d_in[5];
    const float* ml_w1   = (const float*)d_in[6];
    const float* ml_b1   = (const float*)d_in[7];
    const float* ml_w2   = (const float*)d_in[8];
    const float* ml_b2   = (const float*)d_in[9];
    const float* enc_w   = (const float*)d_in[10];
    const float* enc_b   = (const float*)d_in[11];
    const float* ln_g    = (const float*)d_in[12];
    const float* ln_b    = (const float*)d_in[13];
    const float* cls_w1  = (const float*)d_in[14];
    const float* cls_b1  = (const float*)d_in[15];
    const float* prelu_a = (const float*)d_in[16];
    const float* cls_w2  = (const float*)d_in[17];
    const float* cls_b2  = (const float*)d_in[18];

    float* out = (float*)d_out;
    float* out_pred = out;                       // [50000, 2]
    float* out_z    = out + 100000;              // [50000, 128]
    float* out_avec = out + 100000 + NN * NHID;  // [1, 32, 128]
    float* out_alog = out_avec + NA * NHID;      // [32, 2]

    float *p_tmp, *p_h, *p_hx, *p_haB, *p_attn, *p_rowsum, *p_colsum;
    float *p_support, *p_U, *p_xcA, *p_xcB, *p_t1;
    cudaGetSymbolAddress((void**)&p_tmp,     g_tmp);
    cudaGetSymbolAddress((void**)&p_h,       g_h);
    cudaGetSymbolAddress((void**)&p_hx,      g_hx);
    cudaGetSymbolAddress((void**)&p_haB,     g_haB);
    cudaGetSymbolAddress((void**)&p_attn,    g_attn);
    cudaGetSymbolAddress((void**)&p_rowsum,  g_rowsum);
    cudaGetSymbolAddress((void**)&p_colsum,  g_colsum);
    cudaGetSymbolAddress((void**)&p_support, g_support);
    cudaGetSymbolAddress((void**)&p_U,       g_U);
    cudaGetSymbolAddress((void**)&p_xcA,     g_xcA);
    cudaGetSymbolAddress((void**)&p_xcB,     g_xcB);
    cudaGetSymbolAddress((void**)&p_t1,      g_t1);

    const int MB = (NN + 127) / 128;             // 391
    const dim3 g1(1, MB);
    const int TG_SMEM = 32768;                   // 4 arrays * 2 stages * 1024 u32

    cudaFuncSetAttribute(tgemm_kernel<0>, cudaFuncAttributeMaxDynamicSharedMemorySize, TG_SMEM);
    cudaFuncSetAttribute(tgemm_kernel<1>, cudaFuncAttributeMaxDynamicSharedMemorySize, TG_SMEM);
    cudaFuncSetAttribute(tgemm_kernel<2>, cudaFuncAttributeMaxDynamicSharedMemorySize, TG_SMEM);
    cudaFuncSetAttribute(attn_kernel, cudaFuncAttributeMaxDynamicSharedMemorySize, 102400);

    // anchor-side precomputes (independent)
    hab_kernel<<<dim3(NA, NP), NHID>>>(anchors, ml_w1, ml_b1, p_haB);
    anchor_kernel<<<1, 128>>>(anchors, cls_w1, cls_b1, prelu_a, cls_w2, cls_b2,
                              out_avec, out_alog);

    // input MLP: h = relu(x@W1+b1)@W2+b2
    tgemm_kernel<1><<<g1, 512, TG_SMEM>>>(x, im_w1, im_b1, nullptr, p_tmp,
                                          NN, NFEAT, NFEAT, 0, NHID);
    tgemm_kernel<0><<<g1, 512, TG_SMEM>>>(p_tmp, im_w2, im_b2, nullptr, p_h,
                                          NN, NHID, NHID, 0, NHID);

    // hx[p] = h @ Wx[p] -> interleaved [n][p*128+j], fused: grid.x = p
    tgemm_kernel<0><<<dim3(NP, MB), 512, TG_SMEM>>>(p_h, ml_w1, nullptr, nullptr,
                                                    p_hx, NN, NHID, NHID,
                                                    (long)2 * NHID * NHID, NP * NHID);

    cudaMemsetAsync(p_colsum, 0, NA * sizeof(float));
    attn_kernel<<<NN / 16, 256, 102400>>>(p_hx, p_haB, ml_w2, ml_b2,
                                          p_attn, p_rowsum, p_colsum);

    // 2-hop encoder
    const float* xc_in = p_h;
    float* xcs[2] = { p_xcA, p_xcB };
    for (int hop = 0; hop < 2; hop++) {
        tgemm_kernel<0><<<g1, 512, TG_SMEM>>>(xc_in, enc_w + (size_t)hop * NHID * NHID,
                                              nullptr, nullptr, p_support,
                                              NN, NHID, NHID, 0, NHID);
        cudaMemsetAsync(p_U, 0, NA * NHID * sizeof(float));
        agg_kernel<<<(NN + 255) / 256, 256>>>(p_attn, p_support, p_U, NN);
        xc_kernel<<<(NN + 31) / 32, 128>>>(p_attn, p_rowsum, p_colsum, p_U,
                                           enc_b + hop * NHID, xcs[hop], NN);
        xc_in = xcs[hop];
    }

    // z = LN(xc + h) -> out_z ; classifier
    ln_kernel<<<NN / 8, 256>>>(xc_in, p_h, ln_g, ln_b, out_z, NN);
    tgemm_kernel<2><<<g1, 512, TG_SMEM>>>(out_z, cls_w1, cls_b1, prelu_a, p_t1,
                                          NN, NHID, NHID, 0, NHID);
    pred_kernel<<<NN / 8, 256>>>(p_t1, cls_w2, cls_b2, out_pred, NN);
}